// round 4
// baseline (speedup 1.0000x reference)
#include <cuda_runtime.h>
#include <math.h>

#define M_NODES 16384
#define D_DIM   128
#define N_NBR   32
#define H_HEADS 8
#define DH_DIM  16
#define R_REL   237
#define LN_EPS  1e-5f
#define ATT_SCALE 0.25f   // 16^-0.5

// ---------------- scratch (static device globals; no allocs allowed) --------
__device__ float g_Q [M_NODES * D_DIM];
__device__ float g_KX[M_NODES * D_DIM];
__device__ float g_VX[M_NODES * D_DIM];
__device__ float g_RK[R_REL   * D_DIM];
__device__ float g_Att[M_NODES * D_DIM];
__device__ int   g_flags[2];   // [0]=indices are int64, [1]=mask is int32

// ---------------------------------------------------------------------------
// dtype probe: deterministic, tiny. Writes g_flags.
// ---------------------------------------------------------------------------
__global__ void detect_dtypes(const int* __restrict__ nidx_w,
                              const unsigned char* __restrict__ mask_b)
{
    if (threadIdx.x == 0) {
        int odd_nonzero = 0;
        for (int i = 1; i < 512; i += 2) odd_nonzero |= (nidx_w[i] != 0);
        g_flags[0] = !odd_nonzero;

        int hi_nonzero = 0;
        for (int i = 0; i < 1024; i++)
            if ((i & 3) != 0) hi_nonzero |= (mask_b[i] != 0);
        g_flags[1] = !hi_nonzero;
    }
}

// ---------------------------------------------------------------------------
// Fused projection GEMM. grid = (130, 3):
//   y=0: Q  = X @ Wq + bq          (x in [0,128))
//   y=1: KX = X @ Wk               (x in [0,128))
//        RK = rel @ Wk + bk        (x in [128,130))
//   y=2: VX = X @ Wv + bv          (x in [0,128))
// Block: 256 thr, 128x128 tile, 8x8 register micro-tiles, k-chunks of 32.
// ---------------------------------------------------------------------------
__global__ __launch_bounds__(256) void gemm_qkv(
    const float* __restrict__ X, const float* __restrict__ rel,
    const float* __restrict__ Wq, const float* __restrict__ bq,
    const float* __restrict__ Wk, const float* __restrict__ bk,
    const float* __restrict__ Wv, const float* __restrict__ bv,
    float* __restrict__ Q, float* __restrict__ KX,
    float* __restrict__ VX, float* __restrict__ RK)
{
    const int bx = blockIdx.x, by = blockIdx.y;
    if (by != 1 && bx >= 128) return;

    const float *Xp, *W, *bias;
    float* Out;
    int rows, row0;
    if (by == 0)      { Xp = X;  W = Wq; bias = bq; Out = Q;  rows = M_NODES; row0 = bx * 128; }
    else if (by == 2) { Xp = X;  W = Wv; bias = bv; Out = VX; rows = M_NODES; row0 = bx * 128; }
    else if (bx < 128){ Xp = X;  W = Wk; bias = 0;  Out = KX; rows = M_NODES; row0 = bx * 128; }
    else              { Xp = rel;W = Wk; bias = bk; Out = RK; rows = R_REL;   row0 = (bx - 128) * 128; }

    __shared__ float smem[32 * 132 + 32 * 128];   // sXt (transposed X) | sW
    float* sXt = smem;              // [32][132]
    float* sW  = smem + 32 * 132;   // [32][128]

    const int tid = threadIdx.x;
    const int tx = tid & 15, ty = tid >> 4;

    float acc[8][8];
#pragma unroll
    for (int i = 0; i < 8; i++)
#pragma unroll
        for (int j = 0; j < 8; j++) acc[i][j] = 0.f;

    for (int k0 = 0; k0 < 128; k0 += 32) {
#pragma unroll
        for (int it = 0; it < 4; it++) {
            int i  = tid + it * 256;          // 0..1023 (float4 units)
            int kk = i >> 5, cq = i & 31;
            reinterpret_cast<float4*>(&sW[kk * 128])[cq] =
                reinterpret_cast<const float4*>(W + (size_t)(k0 + kk) * 128)[cq];
        }
#pragma unroll
        for (int it = 0; it < 4; it++) {
            int i  = tid + it * 256;          // 0..1023
            int r  = i >> 3, kq = i & 7;
            float4 v = make_float4(0.f, 0.f, 0.f, 0.f);
            if (row0 + r < rows)
                v = reinterpret_cast<const float4*>(Xp + (size_t)(row0 + r) * 128 + k0)[kq];
            sXt[(kq * 4 + 0) * 132 + r] = v.x;
            sXt[(kq * 4 + 1) * 132 + r] = v.y;
            sXt[(kq * 4 + 2) * 132 + r] = v.z;
            sXt[(kq * 4 + 3) * 132 + r] = v.w;
        }
        __syncthreads();
#pragma unroll
        for (int kk = 0; kk < 32; kk++) {
            float4 a0 = *reinterpret_cast<const float4*>(&sXt[kk * 132 + ty * 8]);
            float4 a1 = *reinterpret_cast<const float4*>(&sXt[kk * 132 + ty * 8 + 4]);
            float4 b0 = *reinterpret_cast<const float4*>(&sW [kk * 128 + tx * 8]);
            float4 b1 = *reinterpret_cast<const float4*>(&sW [kk * 128 + tx * 8 + 4]);
            float a[8] = {a0.x, a0.y, a0.z, a0.w, a1.x, a1.y, a1.z, a1.w};
            float b[8] = {b0.x, b0.y, b0.z, b0.w, b1.x, b1.y, b1.z, b1.w};
#pragma unroll
            for (int i = 0; i < 8; i++)
#pragma unroll
                for (int j = 0; j < 8; j++) acc[i][j] = fmaf(a[i], b[j], acc[i][j]);
        }
        __syncthreads();
    }

    float bb[8];
#pragma unroll
    for (int j = 0; j < 8; j++) bb[j] = bias ? bias[tx * 8 + j] : 0.f;

#pragma unroll
    for (int i = 0; i < 8; i++) {
        int r = row0 + ty * 8 + i;
        if (r < rows) {
            float4 o0 = make_float4(acc[i][0] + bb[0], acc[i][1] + bb[1],
                                    acc[i][2] + bb[2], acc[i][3] + bb[3]);
            float4 o1 = make_float4(acc[i][4] + bb[4], acc[i][5] + bb[5],
                                    acc[i][6] + bb[6], acc[i][7] + bb[7]);
            *reinterpret_cast<float4*>(Out + (size_t)r * 128 + tx * 8)     = o0;
            *reinterpret_cast<float4*>(Out + (size_t)r * 128 + tx * 8 + 4) = o1;
        }
    }
}

// ---------------------------------------------------------------------------
// Attention: one 128-thread block per node. float4 gathers from L2-resident
// tables (24 LDG.128/thread instead of 96 LDG.32), scores via intra-16-lane
// shfl reduction, small softmax, AV.
// ---------------------------------------------------------------------------
__global__ __launch_bounds__(128) void attn_kernel(
    const void* __restrict__ nidx_v, const void* __restrict__ rids_v,
    const void* __restrict__ mask_v)
{
    __shared__ float ksh[32][128];
    __shared__ float vsh[32][128];
    __shared__ float sc[8][33];
    __shared__ int s_idx[32], s_rel[32], s_msk[32];

    const int m = blockIdx.x;
    const int j = threadIdx.x;
    const int h = j >> 4;

    if (j < 32) {
        size_t pos = (size_t)m * 32 + j;
        int idx64  = g_flags[0];
        int msk32  = g_flags[1];
        int mk;
        if (msk32) mk = ((const int*)mask_v)[pos] != 0;
        else       mk = ((const unsigned char*)mask_v)[pos] != 0;
        int idx, rel;
        if (idx64) {
            idx = (int)((const long long*)nidx_v)[pos];
            rel = (int)((const long long*)rids_v)[pos];
        } else {
            idx = ((const int*)nidx_v)[pos];
            rel = ((const int*)rids_v)[pos];
        }
        s_msk[j] = mk;
        s_idx[j] = mk ? idx : 0;
        s_rel[j] = mk ? rel : 0;
    }
    float qj = g_Q[(size_t)m * 128 + j];
    __syncthreads();

    // vectorized gather: thread -> (row-group r, quad q4)
    const int q4 = (j & 31) * 4;
    const int r  = j >> 5;
#pragma unroll
    for (int n0 = 0; n0 < 32; n0 += 4) {
        int n   = n0 + r;
        int src = s_idx[n] * 128;
        float4 k4 = *reinterpret_cast<const float4*>(g_KX + src + q4);
        float4 rk = *reinterpret_cast<const float4*>(g_RK + s_rel[n] * 128 + q4);
        float4 v4 = *reinterpret_cast<const float4*>(g_VX + src + q4);
        k4.x += rk.x; k4.y += rk.y; k4.z += rk.z; k4.w += rk.w;
        *reinterpret_cast<float4*>(&ksh[n][q4]) = k4;
        *reinterpret_cast<float4*>(&vsh[n][q4]) = v4;
    }
    __syncthreads();

#pragma unroll 4
    for (int n = 0; n < 32; n++) {
        float p = qj * ksh[n][j];
        p += __shfl_xor_sync(0xffffffffu, p, 8);
        p += __shfl_xor_sync(0xffffffffu, p, 4);
        p += __shfl_xor_sync(0xffffffffu, p, 2);
        p += __shfl_xor_sync(0xffffffffu, p, 1);
        if ((j & 15) == 0) sc[h][n] = p;
    }
    __syncthreads();

    if (j < 8) {
        float mx = -1e30f;
#pragma unroll
        for (int n = 0; n < 32; n++) {
            float s = s_msk[n] ? sc[j][n] * ATT_SCALE : -1e30f;
            sc[j][n] = s;
            mx = fmaxf(mx, s);
        }
        float sum = 0.f;
#pragma unroll
        for (int n = 0; n < 32; n++) {
            float e = __expf(sc[j][n] - mx);   // masked: exp(~-1e30) underflows to 0
            sc[j][n] = e;
            sum += e;
        }
        float inv = 1.f / sum;
#pragma unroll
        for (int n = 0; n < 32; n++) sc[j][n] *= inv;
    }
    __syncthreads();

    float acc = 0.f;
#pragma unroll
    for (int n = 0; n < 32; n++) acc = fmaf(sc[h][n], vsh[n][j], acc);
    g_Att[(size_t)m * 128 + j] = acc;
}

// ---------------------------------------------------------------------------
// Out = LN(entity + Att @ Wo + bo). Same GEMM mainloop + fused LN epilogue.
// rows = 16384 (multiple of 128, no guards needed).
// ---------------------------------------------------------------------------
__global__ __launch_bounds__(256) void out_ln_kernel(
    const float* __restrict__ Att, const float* __restrict__ Wo,
    const float* __restrict__ bo,  const float* __restrict__ ent,
    const float* __restrict__ gamma, const float* __restrict__ beta,
    float* __restrict__ Out)
{
    __shared__ float smem[32 * 132 + 32 * 128];
    float* sXt = smem;
    float* sW  = smem + 32 * 132;

    const int tid = threadIdx.x;
    const int tx = tid & 15, ty = tid >> 4;
    const int row0 = blockIdx.x * 128;

    float acc[8][8];
#pragma unroll
    for (int i = 0; i < 8; i++)
#pragma unroll
        for (int j = 0; j < 8; j++) acc[i][j] = 0.f;

    for (int k0 = 0; k0 < 128; k0 += 32) {
#pragma unroll
        for (int it = 0; it < 4; it++) {
            int i  = tid + it * 256;
            int kk = i >> 5, cq = i & 31;
            reinterpret_cast<float4*>(&sW[kk * 128])[cq] =
                reinterpret_cast<const float4*>(Wo + (size_t)(k0 + kk) * 128)[cq];
        }
#pragma unroll
        for (int it = 0; it < 4; it++) {
            int i  = tid + it * 256;
            int r  = i >> 3, kq = i & 7;
            float4 v = reinterpret_cast<const float4*>(Att + (size_t)(row0 + r) * 128 + k0)[kq];
            sXt[(kq * 4 + 0) * 132 + r] = v.x;
            sXt[(kq * 4 + 1) * 132 + r] = v.y;
            sXt[(kq * 4 + 2) * 132 + r] = v.z;
            sXt[(kq * 4 + 3) * 132 + r] = v.w;
        }
        __syncthreads();
#pragma unroll
        for (int kk = 0; kk < 32; kk++) {
            float4 a0 = *reinterpret_cast<const float4*>(&sXt[kk * 132 + ty * 8]);
            float4 a1 = *reinterpret_cast<const float4*>(&sXt[kk * 132 + ty * 8 + 4]);
            float4 b0 = *reinterpret_cast<const float4*>(&sW [kk * 128 + tx * 8]);
            float4 b1 = *reinterpret_cast<const float4*>(&sW [kk * 128 + tx * 8 + 4]);
            float a[8] = {a0.x, a0.y, a0.z, a0.w, a1.x, a1.y, a1.z, a1.w};
            float b[8] = {b0.x, b0.y, b0.z, b0.w, b1.x, b1.y, b1.z, b1.w};
#pragma unroll
            for (int i = 0; i < 8; i++)
#pragma unroll
                for (int j = 0; j < 8; j++) acc[i][j] = fmaf(a[i], b[j], acc[i][j]);
        }
        __syncthreads();
    }

    // epilogue: + bo + residual, then LayerNorm per row
    float bb[8], gg[8], be[8];
#pragma unroll
    for (int j = 0; j < 8; j++) {
        int c = tx * 8 + j;
        bb[j] = bo[c]; gg[j] = gamma[c]; be[j] = beta[c];
    }

    float ps[8], pq[8];
#pragma unroll
    for (int i = 0; i < 8; i++) {
        int r = row0 + ty * 8 + i;
        float4 e0 = *reinterpret_cast<const float4*>(ent + (size_t)r * 128 + tx * 8);
        float4 e1 = *reinterpret_cast<const float4*>(ent + (size_t)r * 128 + tx * 8 + 4);
        float ev[8] = {e0.x, e0.y, e0.z, e0.w, e1.x, e1.y, e1.z, e1.w};
        float s1 = 0.f, s2 = 0.f;
#pragma unroll
        for (int j = 0; j < 8; j++) {
            float v = acc[i][j] + bb[j] + ev[j];
            acc[i][j] = v;
            s1 += v;
            s2 = fmaf(v, v, s2);
        }
        ps[i] = s1; pq[i] = s2;
    }

    float* red1 = smem;          // [128][16]
    float* red2 = smem + 2048;   // [128][16]
#pragma unroll
    for (int i = 0; i < 8; i++) {
        int rl = ty * 8 + i;
        red1[rl * 16 + tx] = ps[i];
        red2[rl * 16 + tx] = pq[i];
    }
    __syncthreads();

#pragma unroll
    for (int i = 0; i < 8; i++) {
        int rl = ty * 8 + i;
        float s1 = 0.f, s2 = 0.f;
#pragma unroll
        for (int t = 0; t < 16; t++) { s1 += red1[rl * 16 + t]; s2 += red2[rl * 16 + t]; }
        float mu   = s1 * (1.f / 128.f);
        float var  = s2 * (1.f / 128.f) - mu * mu;
        float rstd = rsqrtf(var + LN_EPS);
        int r = row0 + rl;
        float o[8];
#pragma unroll
        for (int j = 0; j < 8; j++)
            o[j] = (acc[i][j] - mu) * rstd * gg[j] + be[j];
        *reinterpret_cast<float4*>(Out + (size_t)r * 128 + tx * 8)     = make_float4(o[0], o[1], o[2], o[3]);
        *reinterpret_cast<float4*>(Out + (size_t)r * 128 + tx * 8 + 4) = make_float4(o[4], o[5], o[6], o[7]);
    }
}

// ---------------------------------------------------------------------------
extern "C" void kernel_launch(void* const* d_in, const int* in_sizes, int n_in,
                              void* d_out, int out_size)
{
    const float* ent  = (const float*)d_in[0];
    const void*  nidx = d_in[1];
    const void*  rids = d_in[2];
    const void*  mask = d_in[3];
    const float* Wq = (const float*)d_in[4];
    const float* bq = (const float*)d_in[5];
    const float* Wk = (const float*)d_in[6];
    const float* bk = (const float*)d_in[7];
    const float* Wv = (const float*)d_in[8];
    const float* bv = (const float*)d_in[9];
    const float* Wo = (const float*)d_in[10];
    const float* bo = (const float*)d_in[11];
    const float* rel_table = (const float*)d_in[12];
    const float* gamma = (const float*)d_in[13];
    const float* beta  = (const float*)d_in[14];
    float* out = (float*)d_out;

    void *pQ, *pKX, *pVX, *pRK, *pAtt;
    cudaGetSymbolAddress(&pQ,  g_Q);
    cudaGetSymbolAddress(&pKX, g_KX);
    cudaGetSymbolAddress(&pVX, g_VX);
    cudaGetSymbolAddress(&pRK, g_RK);
    cudaGetSymbolAddress(&pAtt, g_Att);

    detect_dtypes<<<1, 32>>>((const int*)nidx, (const unsigned char*)mask);

    gemm_qkv<<<dim3(130, 3), 256>>>(ent, rel_table, Wq, bq, Wk, bk, Wv, bv,
                                    (float*)pQ, (float*)pKX, (float*)pVX, (float*)pRK);

    attn_kernel<<<M_NODES, 128>>>(nidx, rids, mask);

    out_ln_kernel<<<M_NODES / 128, 256>>>((const float*)pAtt, Wo, bo, ent, gamma, beta, out);
}

// round 6
// speedup vs baseline: 1.6350x; 1.6350x over previous
#include <cuda_runtime.h>
#include <math.h>

#define M_NODES 16384
#define D_DIM   128
#define N_NBR   32
#define H_HEADS 8
#define DH_DIM  16
#define R_REL   237
#define LN_EPS  1e-5f
#define ATT_SCALE 0.25f   // 16^-0.5

// ---------------- scratch (static device globals; no allocs allowed) --------
__device__ float g_Q [M_NODES * D_DIM];
__device__ float g_KX[M_NODES * D_DIM];
__device__ float g_VX[M_NODES * D_DIM];
__device__ float g_RK[R_REL   * D_DIM];
__device__ float g_Att[M_NODES * D_DIM];
__device__ int   g_flags[2];   // [0]=indices are int64, [1]=mask is int32

// ---------------------------------------------------------------------------
// dtype probe: parallel over 1024 threads, block-wide OR reduction.
// ---------------------------------------------------------------------------
__global__ void detect_dtypes(const int* __restrict__ nidx_w,
                              const unsigned char* __restrict__ mask_b)
{
    const int t = threadIdx.x;
    int odd = 0, hi = 0;
    // int64 detection: odd int32 words over first 512 words (256 checks)
    if (t < 256) odd = (nidx_w[2 * t + 1] != 0);
    // mask int32 detection: bytes at %4!=0 over first 1024 bytes
    if ((t & 3) != 0) hi = (mask_b[t] != 0);
    odd = __syncthreads_or(odd);
    hi  = __syncthreads_or(hi);
    if (t == 0) { g_flags[0] = !odd; g_flags[1] = !hi; }
}

// ---------------------------------------------------------------------------
// GEMM: Out[rows,128] = X[rows,128] @ W[128,128] (+ bias). Block: 256 thr,
// 128x128 output tile, 8x8 register micro-tiles, k-chunks of 32.
// ---------------------------------------------------------------------------
__global__ __launch_bounds__(256) void gemm_proj(
    const float* __restrict__ X, const float* __restrict__ W,
    const float* __restrict__ bias, float* __restrict__ Out, int rows)
{
    __shared__ float smem[32 * 132 + 32 * 128];   // sXt (transposed X) | sW
    float* sXt = smem;              // [32][132]
    float* sW  = smem + 32 * 132;   // [32][128]

    const int tid = threadIdx.x;
    const int tx = tid & 15, ty = tid >> 4;
    const int row0 = blockIdx.x * 128;

    float acc[8][8];
#pragma unroll
    for (int i = 0; i < 8; i++)
#pragma unroll
        for (int j = 0; j < 8; j++) acc[i][j] = 0.f;

    for (int k0 = 0; k0 < 128; k0 += 32) {
#pragma unroll
        for (int it = 0; it < 4; it++) {
            int i  = tid + it * 256;          // 0..1023 (float4 units)
            int kk = i >> 5, cq = i & 31;
            reinterpret_cast<float4*>(&sW[kk * 128])[cq] =
                reinterpret_cast<const float4*>(W + (size_t)(k0 + kk) * 128)[cq];
        }
#pragma unroll
        for (int it = 0; it < 4; it++) {
            int i  = tid + it * 256;          // 0..1023
            int r  = i >> 3, kq = i & 7;
            float4 v = make_float4(0.f, 0.f, 0.f, 0.f);
            if (row0 + r < rows)
                v = reinterpret_cast<const float4*>(X + (size_t)(row0 + r) * 128 + k0)[kq];
            sXt[(kq * 4 + 0) * 132 + r] = v.x;
            sXt[(kq * 4 + 1) * 132 + r] = v.y;
            sXt[(kq * 4 + 2) * 132 + r] = v.z;
            sXt[(kq * 4 + 3) * 132 + r] = v.w;
        }
        __syncthreads();
#pragma unroll
        for (int kk = 0; kk < 32; kk++) {
            float4 a0 = *reinterpret_cast<const float4*>(&sXt[kk * 132 + ty * 8]);
            float4 a1 = *reinterpret_cast<const float4*>(&sXt[kk * 132 + ty * 8 + 4]);
            float4 b0 = *reinterpret_cast<const float4*>(&sW [kk * 128 + tx * 8]);
            float4 b1 = *reinterpret_cast<const float4*>(&sW [kk * 128 + tx * 8 + 4]);
            float a[8] = {a0.x, a0.y, a0.z, a0.w, a1.x, a1.y, a1.z, a1.w};
            float b[8] = {b0.x, b0.y, b0.z, b0.w, b1.x, b1.y, b1.z, b1.w};
#pragma unroll
            for (int i = 0; i < 8; i++)
#pragma unroll
                for (int j = 0; j < 8; j++) acc[i][j] = fmaf(a[i], b[j], acc[i][j]);
        }
        __syncthreads();
    }

    float bb[8];
#pragma unroll
    for (int j = 0; j < 8; j++) bb[j] = bias ? bias[tx * 8 + j] : 0.f;

#pragma unroll
    for (int i = 0; i < 8; i++) {
        int r = row0 + ty * 8 + i;
        if (r < rows) {
            float4 o0 = make_float4(acc[i][0] + bb[0], acc[i][1] + bb[1],
                                    acc[i][2] + bb[2], acc[i][3] + bb[3]);
            float4 o1 = make_float4(acc[i][4] + bb[4], acc[i][5] + bb[5],
                                    acc[i][6] + bb[6], acc[i][7] + bb[7]);
            *reinterpret_cast<float4*>(Out + (size_t)r * 128 + tx * 8)     = o0;
            *reinterpret_cast<float4*>(Out + (size_t)r * 128 + tx * 8 + 4) = o1;
        }
    }
}

// ---------------------------------------------------------------------------
// Attention: one WARP per node. Lane j owns dims [4j,4j+4) (head = j>>2).
// Scores via dot4 + quad shfl reduction; softmax fully register-resident
// (redundant per lane, no block sync); AV accumulated in registers.
// ---------------------------------------------------------------------------
__global__ __launch_bounds__(256) void attn_kernel(
    const void* __restrict__ nidx_v, const void* __restrict__ rids_v,
    const void* __restrict__ mask_v)
{
    __shared__ int s_idx[8][32];
    __shared__ int s_rel[8][32];

    const int warp = threadIdx.x >> 5;
    const int lane = threadIdx.x & 31;
    const int m = blockIdx.x * 8 + warp;

    // neighbor metadata: lane n loads neighbor n
    {
        size_t pos = (size_t)m * 32 + lane;
        const int idx64 = g_flags[0];
        const int msk32 = g_flags[1];
        int mk;
        if (msk32) mk = ((const int*)mask_v)[pos] != 0;
        else       mk = ((const unsigned char*)mask_v)[pos] != 0;
        int idx, rel;
        if (idx64) {
            idx = (int)((const long long*)nidx_v)[pos];
            rel = (int)((const long long*)rids_v)[pos];
        } else {
            idx = ((const int*)nidx_v)[pos];
            rel = ((const int*)rids_v)[pos];
        }
        s_idx[warp][lane] = mk ? idx : 0;
        s_rel[warp][lane] = mk ? rel : 0;
    }
    const unsigned mbits = __ballot_sync(0xffffffffu,
        (g_flags[1] ? ((const int*)mask_v)[(size_t)m * 32 + lane]
                    : (int)((const unsigned char*)mask_v)[(size_t)m * 32 + lane]) != 0);
    __syncwarp();

    const float4 q4 = *reinterpret_cast<const float4*>(g_Q + (size_t)m * 128 + lane * 4);

    // scores: s[n] = (q . (KX[idx]+RK[rel]))_head * scale, masked
    float sc[32];
#pragma unroll
    for (int n = 0; n < 32; n++) {
        const float* kp = g_KX + (size_t)s_idx[warp][n] * 128 + lane * 4;
        const float* rp = g_RK + (size_t)s_rel[warp][n] * 128 + lane * 4;
        float4 k4 = *reinterpret_cast<const float4*>(kp);
        float4 r4 = *reinterpret_cast<const float4*>(rp);
        float p = q4.x * (k4.x + r4.x) + q4.y * (k4.y + r4.y)
                + q4.z * (k4.z + r4.z) + q4.w * (k4.w + r4.w);
        p += __shfl_xor_sync(0xffffffffu, p, 1);
        p += __shfl_xor_sync(0xffffffffu, p, 2);
        sc[n] = ((mbits >> n) & 1u) ? p * ATT_SCALE : -1e30f;
    }

    // softmax over n (per lane; lanes of a quad hold identical values)
    float mx = -1e30f;
#pragma unroll
    for (int n = 0; n < 32; n++) mx = fmaxf(mx, sc[n]);
    float sum = 0.f;
#pragma unroll
    for (int n = 0; n < 32; n++) {
        float e = __expf(sc[n] - mx);   // masked lanes underflow to 0
        sc[n] = e;
        sum += e;
    }
    const float inv = 1.f / sum;

    // AV: acc4 = sum_n p[n] * V[idx[n]][4j..4j+3]
    float4 acc = make_float4(0.f, 0.f, 0.f, 0.f);
#pragma unroll
    for (int n = 0; n < 32; n++) {
        float p = sc[n] * inv;
        float4 v4 = *reinterpret_cast<const float4*>(
            g_VX + (size_t)s_idx[warp][n] * 128 + lane * 4);
        acc.x = fmaf(p, v4.x, acc.x);
        acc.y = fmaf(p, v4.y, acc.y);
        acc.z = fmaf(p, v4.z, acc.z);
        acc.w = fmaf(p, v4.w, acc.w);
    }
    *reinterpret_cast<float4*>(g_Att + (size_t)m * 128 + lane * 4) = acc;
}

// ---------------------------------------------------------------------------
// Out = LN(entity + Att @ Wo + bo). Same GEMM mainloop + fused LN epilogue.
// rows = 16384 (multiple of 128, no guards needed).
// ---------------------------------------------------------------------------
__global__ __launch_bounds__(256) void out_ln_kernel(
    const float* __restrict__ Att, const float* __restrict__ Wo,
    const float* __restrict__ bo,  const float* __restrict__ ent,
    const float* __restrict__ gamma, const float* __restrict__ beta,
    float* __restrict__ Out)
{
    __shared__ float smem[32 * 132 + 32 * 128];
    float* sXt = smem;
    float* sW  = smem + 32 * 132;

    const int tid = threadIdx.x;
    const int tx = tid & 15, ty = tid >> 4;
    const int row0 = blockIdx.x * 128;

    float acc[8][8];
#pragma unroll
    for (int i = 0; i < 8; i++)
#pragma unroll
        for (int j = 0; j < 8; j++) acc[i][j] = 0.f;

    for (int k0 = 0; k0 < 128; k0 += 32) {
#pragma unroll
        for (int it = 0; it < 4; it++) {
            int i  = tid + it * 256;
            int kk = i >> 5, cq = i & 31;
            reinterpret_cast<float4*>(&sW[kk * 128])[cq] =
                reinterpret_cast<const float4*>(Wo + (size_t)(k0 + kk) * 128)[cq];
        }
#pragma unroll
        for (int it = 0; it < 4; it++) {
            int i  = tid + it * 256;
            int r  = i >> 3, kq = i & 7;
            float4 v = reinterpret_cast<const float4*>(Att + (size_t)(row0 + r) * 128 + k0)[kq];
            sXt[(kq * 4 + 0) * 132 + r] = v.x;
            sXt[(kq * 4 + 1) * 132 + r] = v.y;
            sXt[(kq * 4 + 2) * 132 + r] = v.z;
            sXt[(kq * 4 + 3) * 132 + r] = v.w;
        }
        __syncthreads();
#pragma unroll
        for (int kk = 0; kk < 32; kk++) {
            float4 a0 = *reinterpret_cast<const float4*>(&sXt[kk * 132 + ty * 8]);
            float4 a1 = *reinterpret_cast<const float4*>(&sXt[kk * 132 + ty * 8 + 4]);
            float4 b0 = *reinterpret_cast<const float4*>(&sW [kk * 128 + tx * 8]);
            float4 b1 = *reinterpret_cast<const float4*>(&sW [kk * 128 + tx * 8 + 4]);
            float a[8] = {a0.x, a0.y, a0.z, a0.w, a1.x, a1.y, a1.z, a1.w};
            float b[8] = {b0.x, b0.y, b0.z, b0.w, b1.x, b1.y, b1.z, b1.w};
#pragma unroll
            for (int i = 0; i < 8; i++)
#pragma unroll
                for (int j = 0; j < 8; j++) acc[i][j] = fmaf(a[i], b[j], acc[i][j]);
        }
        __syncthreads();
    }

    // epilogue: + bo + residual, then LayerNorm per row
    float bb[8], gg[8], be[8];
#pragma unroll
    for (int j = 0; j < 8; j++) {
        int c = tx * 8 + j;
        bb[j] = bo[c]; gg[j] = gamma[c]; be[j] = beta[c];
    }

    float ps[8], pq[8];
#pragma unroll
    for (int i = 0; i < 8; i++) {
        int r = row0 + ty * 8 + i;
        float4 e0 = *reinterpret_cast<const float4*>(ent + (size_t)r * 128 + tx * 8);
        float4 e1 = *reinterpret_cast<const float4*>(ent + (size_t)r * 128 + tx * 8 + 4);
        float ev[8] = {e0.x, e0.y, e0.z, e0.w, e1.x, e1.y, e1.z, e1.w};
        float s1 = 0.f, s2 = 0.f;
#pragma unroll
        for (int j = 0; j < 8; j++) {
            float v = acc[i][j] + bb[j] + ev[j];
            acc[i][j] = v;
            s1 += v;
            s2 = fmaf(v, v, s2);
        }
        ps[i] = s1; pq[i] = s2;
    }

    float* red1 = smem;          // [128][16]
    float* red2 = smem + 2048;   // [128][16]
#pragma unroll
    for (int i = 0; i < 8; i++) {
        int rl = ty * 8 + i;
        red1[rl * 16 + tx] = ps[i];
        red2[rl * 16 + tx] = pq[i];
    }
    __syncthreads();

#pragma unroll
    for (int i = 0; i < 8; i++) {
        int rl = ty * 8 + i;
        float s1 = 0.f, s2 = 0.f;
#pragma unroll
        for (int t = 0; t < 16; t++) { s1 += red1[rl * 16 + t]; s2 += red2[rl * 16 + t]; }
        float mu   = s1 * (1.f / 128.f);
        float var  = s2 * (1.f / 128.f) - mu * mu;
        float rstd = rsqrtf(var + LN_EPS);
        int r = row0 + rl;
        float o[8];
#pragma unroll
        for (int j = 0; j < 8; j++)
            o[j] = (acc[i][j] - mu) * rstd * gg[j] + be[j];
        *reinterpret_cast<float4*>(Out + (size_t)r * 128 + tx * 8)     = make_float4(o[0], o[1], o[2], o[3]);
        *reinterpret_cast<float4*>(Out + (size_t)r * 128 + tx * 8 + 4) = make_float4(o[4], o[5], o[6], o[7]);
    }
}

// ---------------------------------------------------------------------------
extern "C" void kernel_launch(void* const* d_in, const int* in_sizes, int n_in,
                              void* d_out, int out_size)
{
    const float* ent  = (const float*)d_in[0];
    const void*  nidx = d_in[1];
    const void*  rids = d_in[2];
    const void*  mask = d_in[3];
    const float* Wq = (const float*)d_in[4];
    const float* bq = (const float*)d_in[5];
    const float* Wk = (const float*)d_in[6];
    const float* bk = (const float*)d_in[7];
    const float* Wv = (const float*)d_in[8];
    const float* bv = (const float*)d_in[9];
    const float* Wo = (const float*)d_in[10];
    const float* bo = (const float*)d_in[11];
    const float* rel_table = (const float*)d_in[12];
    const float* gamma = (const float*)d_in[13];
    const float* beta  = (const float*)d_in[14];
    float* out = (float*)d_out;

    void *pQ, *pKX, *pVX, *pRK, *pAtt;
    cudaGetSymbolAddress(&pQ,  g_Q);
    cudaGetSymbolAddress(&pKX, g_KX);
    cudaGetSymbolAddress(&pVX, g_VX);
    cudaGetSymbolAddress(&pRK, g_RK);
    cudaGetSymbolAddress(&pAtt, g_Att);

    detect_dtypes<<<1, 1024>>>((const int*)nidx, (const unsigned char*)mask);

    gemm_proj<<<M_NODES / 128, 256>>>(ent, Wq, bq, (float*)pQ,  M_NODES);
    gemm_proj<<<M_NODES / 128, 256>>>(ent, Wk, (const float*)nullptr, (float*)pKX, M_NODES);
    gemm_proj<<<M_NODES / 128, 256>>>(ent, Wv, bv, (float*)pVX, M_NODES);
    gemm_proj<<<(R_REL + 127) / 128, 256>>>(rel_table, Wk, bk, (float*)pRK, R_REL);

    attn_kernel<<<M_NODES / 8, 256>>>(nidx, rids, mask);

    out_ln_kernel<<<M_NODES / 128, 256>>>((const float*)pAtt, Wo, bo, ent, gamma, beta, out);
}

// round 10
// speedup vs baseline: 2.4938x; 1.5252x over previous
#include <cuda_runtime.h>
#include <math.h>

#define M_NODES 16384
#define D_DIM   128
#define N_NBR   32
#define H_HEADS 8
#define DH_DIM  16
#define R_REL   237
#define LN_EPS  1e-5f
#define ATT_SCALE 0.25f   // 16^-0.5

#define XT_STRIDE 68   // multiple of 4 (16B-aligned float4 reads), not mult of 32

// ---------------- scratch (static device globals; no allocs allowed) --------
__device__ float g_Q [M_NODES * D_DIM];
__device__ float g_KX[M_NODES * D_DIM];
__device__ float g_VX[M_NODES * D_DIM];
__device__ float g_RK[R_REL   * D_DIM];
__device__ float g_Att[M_NODES * D_DIM];
__device__ int   g_flags[2];   // [0]=indices are int64, [1]=mask is int32

// ---------------------------------------------------------------------------
// dtype probe: parallel over 1024 threads, block-wide OR reduction.
// ---------------------------------------------------------------------------
__global__ void detect_dtypes(const int* __restrict__ nidx_w,
                              const unsigned char* __restrict__ mask_b)
{
    const int t = threadIdx.x;
    int odd = 0, hi = 0;
    if (t < 256) odd = (nidx_w[2 * t + 1] != 0);
    if ((t & 3) != 0) hi = (mask_b[t] != 0);
    odd = __syncthreads_or(odd);
    hi  = __syncthreads_or(hi);
    if (t == 0) { g_flags[0] = !odd; g_flags[1] = !hi; }
}

// ---------------------------------------------------------------------------
// Fused projection GEMM, 64x128 tiles. grid = (260, 3):
//   y=0, bx<256 : Q  = X @ Wq + bq
//   y=1, bx<256 : KX = X @ Wk
//   y=1, bx>=256: RK = rel @ Wk + bk   (4 tiles cover 237 rows)
//   y=2, bx<256 : VX = X @ Wv + bv
// Block 256 thr; micro-tile 4 rows x 8 cols; k-chunks of 32.
// ---------------------------------------------------------------------------
__global__ __launch_bounds__(256) void gemm_fused(
    const float* __restrict__ X, const float* __restrict__ rel,
    const float* __restrict__ Wq, const float* __restrict__ bq,
    const float* __restrict__ Wk, const float* __restrict__ bk,
    const float* __restrict__ Wv, const float* __restrict__ bv,
    float* __restrict__ Q, float* __restrict__ KX,
    float* __restrict__ VX, float* __restrict__ RK)
{
    const int bx = blockIdx.x, by = blockIdx.y;
    const float *Xp, *W, *bias;
    float* Out;
    int rows, row0;
    if (by == 0) {
        if (bx >= 256) return;
        Xp = X; W = Wq; bias = bq; Out = Q; rows = M_NODES; row0 = bx * 64;
    } else if (by == 2) {
        if (bx >= 256) return;
        Xp = X; W = Wv; bias = bv; Out = VX; rows = M_NODES; row0 = bx * 64;
    } else if (bx < 256) {
        Xp = X; W = Wk; bias = 0;  Out = KX; rows = M_NODES; row0 = bx * 64;
    } else {
        Xp = rel; W = Wk; bias = bk; Out = RK; rows = R_REL; row0 = (bx - 256) * 64;
    }

    __shared__ float sXt[32 * XT_STRIDE];  // [k][row]
    __shared__ float sW [32 * 128];        // [k][col]

    const int tid = threadIdx.x;
    const int tx = tid & 15, ty = tid >> 4;

    float acc[4][8];
#pragma unroll
    for (int i = 0; i < 4; i++)
#pragma unroll
        for (int j = 0; j < 8; j++) acc[i][j] = 0.f;

    for (int k0 = 0; k0 < 128; k0 += 32) {
        // W chunk [32][128]: 1024 float4, coalesced
#pragma unroll
        for (int it = 0; it < 4; it++) {
            int i  = tid + it * 256;
            int kk = i >> 5, cq = i & 31;
            reinterpret_cast<float4*>(&sW[kk * 128])[cq] =
                reinterpret_cast<const float4*>(W + (size_t)(k0 + kk) * 128)[cq];
        }
        // X chunk [64][32] -> transposed sXt[k][row]: 512 float4
#pragma unroll
        for (int it = 0; it < 2; it++) {
            int i  = tid + it * 256;
            int r  = i >> 3, kq = i & 7;
            float4 v = make_float4(0.f, 0.f, 0.f, 0.f);
            if (row0 + r < rows)
                v = reinterpret_cast<const float4*>(Xp + (size_t)(row0 + r) * 128 + k0)[kq];
            sXt[(kq * 4 + 0) * XT_STRIDE + r] = v.x;
            sXt[(kq * 4 + 1) * XT_STRIDE + r] = v.y;
            sXt[(kq * 4 + 2) * XT_STRIDE + r] = v.z;
            sXt[(kq * 4 + 3) * XT_STRIDE + r] = v.w;
        }
        __syncthreads();
#pragma unroll
        for (int kk = 0; kk < 32; kk++) {
            float4 a4 = *reinterpret_cast<const float4*>(&sXt[kk * XT_STRIDE + ty * 4]);
            float4 b0 = *reinterpret_cast<const float4*>(&sW [kk * 128 + tx * 8]);
            float4 b1 = *reinterpret_cast<const float4*>(&sW [kk * 128 + tx * 8 + 4]);
            float a[4] = {a4.x, a4.y, a4.z, a4.w};
            float b[8] = {b0.x, b0.y, b0.z, b0.w, b1.x, b1.y, b1.z, b1.w};
#pragma unroll
            for (int i = 0; i < 4; i++)
#pragma unroll
                for (int j = 0; j < 8; j++) acc[i][j] = fmaf(a[i], b[j], acc[i][j]);
        }
        __syncthreads();
    }

    float bb[8];
#pragma unroll
    for (int j = 0; j < 8; j++) bb[j] = bias ? bias[tx * 8 + j] : 0.f;

#pragma unroll
    for (int i = 0; i < 4; i++) {
        int r = row0 + ty * 4 + i;
        if (r < rows) {
            float4 o0 = make_float4(acc[i][0] + bb[0], acc[i][1] + bb[1],
                                    acc[i][2] + bb[2], acc[i][3] + bb[3]);
            float4 o1 = make_float4(acc[i][4] + bb[4], acc[i][5] + bb[5],
                                    acc[i][6] + bb[6], acc[i][7] + bb[7]);
            *reinterpret_cast<float4*>(Out + (size_t)r * 128 + tx * 8)     = o0;
            *reinterpret_cast<float4*>(Out + (size_t)r * 128 + tx * 8 + 4) = o1;
        }
    }
}

// ---------------------------------------------------------------------------
// Attention: one WARP per node. Lane j owns dims [4j,4j+4) (head = j>>2).
// Scores via dot4 + quad shfl reduction; softmax fully register-resident
// (redundant per lane, no block sync); AV accumulated in registers.
// ---------------------------------------------------------------------------
__global__ __launch_bounds__(256) void attn_kernel(
    const void* __restrict__ nidx_v, const void* __restrict__ rids_v,
    const void* __restrict__ mask_v)
{
    __shared__ int s_idx[8][32];
    __shared__ int s_rel[8][32];

    const int warp = threadIdx.x >> 5;
    const int lane = threadIdx.x & 31;
    const int m = blockIdx.x * 8 + warp;

    {
        size_t pos = (size_t)m * 32 + lane;
        const int idx64 = g_flags[0];
        const int msk32 = g_flags[1];
        int mk;
        if (msk32) mk = ((const int*)mask_v)[pos] != 0;
        else       mk = ((const unsigned char*)mask_v)[pos] != 0;
        int idx, rel;
        if (idx64) {
            idx = (int)((const long long*)nidx_v)[pos];
            rel = (int)((const long long*)rids_v)[pos];
        } else {
            idx = ((const int*)nidx_v)[pos];
            rel = ((const int*)rids_v)[pos];
        }
        s_idx[warp][lane] = mk ? idx : 0;
        s_rel[warp][lane] = mk ? rel : 0;
    }
    const unsigned mbits = __ballot_sync(0xffffffffu,
        (g_flags[1] ? ((const int*)mask_v)[(size_t)m * 32 + lane]
                    : (int)((const unsigned char*)mask_v)[(size_t)m * 32 + lane]) != 0);
    __syncwarp();

    const float4 q4 = *reinterpret_cast<const float4*>(g_Q + (size_t)m * 128 + lane * 4);

    float sc[32];
#pragma unroll
    for (int n = 0; n < 32; n++) {
        const float* kp = g_KX + (size_t)s_idx[warp][n] * 128 + lane * 4;
        const float* rp = g_RK + (size_t)s_rel[warp][n] * 128 + lane * 4;
        float4 k4 = *reinterpret_cast<const float4*>(kp);
        float4 r4 = *reinterpret_cast<const float4*>(rp);
        float p = q4.x * (k4.x + r4.x) + q4.y * (k4.y + r4.y)
                + q4.z * (k4.z + r4.z) + q4.w * (k4.w + r4.w);
        p += __shfl_xor_sync(0xffffffffu, p, 1);
        p += __shfl_xor_sync(0xffffffffu, p, 2);
        sc[n] = ((mbits >> n) & 1u) ? p * ATT_SCALE : -1e30f;
    }

    float mx = -1e30f;
#pragma unroll
    for (int n = 0; n < 32; n++) mx = fmaxf(mx, sc[n]);
    float sum = 0.f;
#pragma unroll
    for (int n = 0; n < 32; n++) {
        float e = __expf(sc[n] - mx);
        sc[n] = e;
        sum += e;
    }
    const float inv = 1.f / sum;

    float4 acc = make_float4(0.f, 0.f, 0.f, 0.f);
#pragma unroll
    for (int n = 0; n < 32; n++) {
        float p = sc[n] * inv;
        float4 v4 = *reinterpret_cast<const float4*>(
            g_VX + (size_t)s_idx[warp][n] * 128 + lane * 4);
        acc.x = fmaf(p, v4.x, acc.x);
        acc.y = fmaf(p, v4.y, acc.y);
        acc.z = fmaf(p, v4.z, acc.z);
        acc.w = fmaf(p, v4.w, acc.w);
    }
    *reinterpret_cast<float4*>(g_Att + (size_t)m * 128 + lane * 4) = acc;
}

// ---------------------------------------------------------------------------
// Out = LN(entity + Att @ Wo + bo). 64x128 tiles (grid 256), fused LN epilogue.
// ---------------------------------------------------------------------------
__global__ __launch_bounds__(256) void out_ln_kernel(
    const float* __restrict__ Att, const float* __restrict__ Wo,
    const float* __restrict__ bo,  const float* __restrict__ ent,
    const float* __restrict__ gamma, const float* __restrict__ beta,
    float* __restrict__ Out)
{
    __shared__ float sXt[32 * XT_STRIDE];
    __shared__ float sW [32 * 128];

    const int tid = threadIdx.x;
    const int tx = tid & 15, ty = tid >> 4;
    const int row0 = blockIdx.x * 64;

    float acc[4][8];
#pragma unroll
    for (int i = 0; i < 4; i++)
#pragma unroll
        for (int j = 0; j < 8; j++) acc[i][j] = 0.f;

    for (int k0 = 0; k0 < 128; k0 += 32) {
#pragma unroll
        for (int it = 0; it < 4; it++) {
            int i  = tid + it * 256;
            int kk = i >> 5, cq = i & 31;
            reinterpret_cast<float4*>(&sW[kk * 128])[cq] =
                reinterpret_cast<const float4*>(Wo + (size_t)(k0 + kk) * 128)[cq];
        }
#pragma unroll
        for (int it = 0; it < 2; it++) {
            int i  = tid + it * 256;
            int r  = i >> 3, kq = i & 7;
            float4 v = reinterpret_cast<const float4*>(Att + (size_t)(row0 + r) * 128 + k0)[kq];
            sXt[(kq * 4 + 0) * XT_STRIDE + r] = v.x;
            sXt[(kq * 4 + 1) * XT_STRIDE + r] = v.y;
            sXt[(kq * 4 + 2) * XT_STRIDE + r] = v.z;
            sXt[(kq * 4 + 3) * XT_STRIDE + r] = v.w;
        }
        __syncthreads();
#pragma unroll
        for (int kk = 0; kk < 32; kk++) {
            float4 a4 = *reinterpret_cast<const float4*>(&sXt[kk * XT_STRIDE + ty * 4]);
            float4 b0 = *reinterpret_cast<const float4*>(&sW [kk * 128 + tx * 8]);
            float4 b1 = *reinterpret_cast<const float4*>(&sW [kk * 128 + tx * 8 + 4]);
            float a[4] = {a4.x, a4.y, a4.z, a4.w};
            float b[8] = {b0.x, b0.y, b0.z, b0.w, b1.x, b1.y, b1.z, b1.w};
#pragma unroll
            for (int i = 0; i < 4; i++)
#pragma unroll
                for (int j = 0; j < 8; j++) acc[i][j] = fmaf(a[i], b[j], acc[i][j]);
        }
        __syncthreads();
    }

    float bb[8], gg[8], be[8];
#pragma unroll
    for (int j = 0; j < 8; j++) {
        int c = tx * 8 + j;
        bb[j] = bo[c]; gg[j] = gamma[c]; be[j] = beta[c];
    }

    float ps[4], pq[4];
#pragma unroll
    for (int i = 0; i < 4; i++) {
        int r = row0 + ty * 4 + i;
        float4 e0 = *reinterpret_cast<const float4*>(ent + (size_t)r * 128 + tx * 8);
        float4 e1 = *reinterpret_cast<const float4*>(ent + (size_t)r * 128 + tx * 8 + 4);
        float ev[8] = {e0.x, e0.y, e0.z, e0.w, e1.x, e1.y, e1.z, e1.w};
        float s1 = 0.f, s2 = 0.f;
#pragma unroll
        for (int j = 0; j < 8; j++) {
            float v = acc[i][j] + bb[j] + ev[j];
            acc[i][j] = v;
            s1 += v;
            s2 = fmaf(v, v, s2);
        }
        ps[i] = s1; pq[i] = s2;
    }

    float* red1 = sXt;               // [64][16] = 1024 floats
    float* red2 = sXt + 1024;        // [64][16]; 2048 <= 32*68=2176, fits
#pragma unroll
    for (int i = 0; i < 4; i++) {
        int rl = ty * 4 + i;
        red1[rl * 16 + tx] = ps[i];
        red2[rl * 16 + tx] = pq[i];
    }
    __syncthreads();

#pragma unroll
    for (int i = 0; i < 4; i++) {
        int rl = ty * 4 + i;
        float s1 = 0.f, s2 = 0.f;
#pragma unroll
        for (int t = 0; t < 16; t++) { s1 += red1[rl * 16 + t]; s2 += red2[rl * 16 + t]; }
        float mu   = s1 * (1.f / 128.f);
        float var  = s2 * (1.f / 128.f) - mu * mu;
        float rstd = rsqrtf(var + LN_EPS);
        int r = row0 + rl;
        float o[8];
#pragma unroll
        for (int j = 0; j < 8; j++)
            o[j] = (acc[i][j] - mu) * rstd * gg[j] + be[j];
        *reinterpret_cast<float4*>(Out + (size_t)r * 128 + tx * 8)     = make_float4(o[0], o[1], o[2], o[3]);
        *reinterpret_cast<float4*>(Out + (size_t)r * 128 + tx * 8 + 4) = make_float4(o[4], o[5], o[6], o[7]);
    }
}

// ---------------------------------------------------------------------------
extern "C" void kernel_launch(void* const* d_in, const int* in_sizes, int n_in,
                              void* d_out, int out_size)
{
    const float* ent  = (const float*)d_in[0];
    const void*  nidx = d_in[1];
    const void*  rids = d_in[2];
    const void*  mask = d_in[3];
    const float* Wq = (const float*)d_in[4];
    const float* bq = (const float*)d_in[5];
    const float* Wk = (const float*)d_in[6];
    const float* bk = (const float*)d_in[7];
    const float* Wv = (const float*)d_in[8];
    const float* bv = (const float*)d_in[9];
    const float* Wo = (const float*)d_in[10];
    const float* bo = (const float*)d_in[11];
    const float* rel_table = (const float*)d_in[12];
    const float* gamma = (const float*)d_in[13];
    const float* beta  = (const float*)d_in[14];
    float* out = (float*)d_out;

    void *pQ, *pKX, *pVX, *pRK, *pAtt;
    cudaGetSymbolAddress(&pQ,  g_Q);
    cudaGetSymbolAddress(&pKX, g_KX);
    cudaGetSymbolAddress(&pVX, g_VX);
    cudaGetSymbolAddress(&pRK, g_RK);
    cudaGetSymbolAddress(&pAtt, g_Att);

    detect_dtypes<<<1, 1024>>>((const int*)nidx, (const unsigned char*)mask);

    gemm_fused<<<dim3(260, 3), 256>>>(ent, rel_table, Wq, bq, Wk, bk, Wv, bv,
                                      (float*)pQ, (float*)pKX, (float*)pVX, (float*)pRK);

    attn_kernel<<<M_NODES / 8, 256>>>(nidx, rids, mask);

    out_ln_kernel<<<M_NODES / 64, 256>>>((const float*)pAtt, Wo, bo, ent, gamma, beta, out);
}